// round 6
// baseline (speedup 1.0000x reference)
#include <cuda_runtime.h>
#include <math.h>

#define HH 48
#define WW 48
#define CIN 256
#define COUT 256
#define HW 2304          // 48*48
#define M_ANCH 6912      // 3*48*48
#define TOPK 2000
#define NEGV -1000000000.0f
#define IMGSZ 768.0f
#define OBJ_THR 0.3f
#define IOU_THR 0.7f

#define NB 128           // persistent blocks (1/SM guaranteed by smem usage)
#define NT 576           // threads per block
#define SORT_SPLIT 8
#define SEG (M_ANCH / SORT_SPLIT)   // 864

// ---------------- scratch (no allocations allowed) ----------------
__device__ float g_inter[COUT * HW];
__device__ float g_skey[M_ANCH];
__device__ float g_boxes[M_ANCH * 4];
__device__ int   g_rank[M_ANCH];
__device__ int   g_order[M_ANCH];
__device__ unsigned int g_barc;          // barrier arrival counter (returns to 0)
__device__ volatile unsigned int g_barg; // barrier generation (monotonic)

// software grid barrier: all NB blocks must participate every time
__device__ __forceinline__ void gsync() {
    __syncthreads();
    if (threadIdx.x == 0) {
        const unsigned int gen = g_barg;
        __threadfence();
        if (atomicAdd(&g_barc, 1u) == NB - 1u) {
            g_barc = 0u;
            __threadfence();
            g_barg = gen + 1u;
        } else {
            while (g_barg == gen) { }
        }
    }
    __syncthreads();
}

__device__ __forceinline__ float iou_f(float a0, float a1, float a2, float a3,
                                       float areai,
                                       float c0, float c1, float c2, float c3) {
    float iw = fminf(a2, c2) - fmaxf(a0, c0);
    float ih = fminf(a3, c3) - fmaxf(a1, c1);
    iw = fmaxf(iw, 0.0f);
    ih = fmaxf(ih, 0.0f);
    const float inter = iw * ih;
    const float areaj = (c2 - c0) * (c3 - c1);
    return inter / fmaxf(areai + areaj - inter, 1e-9f);
}

#define NMS_SMEM (5 * M_ANCH * 4 + M_ANCH)   // 145152 bytes dynamic

__global__ __launch_bounds__(NT, 1)
void fused_kernel(const float* __restrict__ x,
                  const float* __restrict__ wgt,
                  const float* __restrict__ bias,
                  const float* __restrict__ det_w,
                  const float* __restrict__ det_b,
                  const float* __restrict__ reg_w,
                  const float* __restrict__ reg_b,
                  const float* __restrict__ anchors,
                  float* __restrict__ out) {
    __shared__ float s_xs[50 * 50];          // conv input plane / sort segment
    __shared__ float s_wsm[2 * CIN * 9];     // conv weights for the block's 2 channels
    extern __shared__ float dyn[];           // nms scratch (block 0 only)

    const int b = blockIdx.x;
    const int t = threadIdx.x;

    // ================= phase 1: conv (block b -> channels b, b+NB) ===========
    {
        const int co0 = b, co1 = b + NB;
        const int ty = t / 24, tx = t % 24;

        for (int idx = t; idx < CIN * 9; idx += NT)
            s_wsm[idx] = wgt[co0 * CIN * 9 + idx];
        for (int idx = t; idx < CIN * 9; idx += NT)
            s_wsm[CIN * 9 + idx] = wgt[co1 * CIN * 9 + idx];

        int  goff[5]; bool gval[5]; int sidx[5];
#pragma unroll
        for (int u = 0; u < 5; u++) {
            const int idx = t + u * NT;
            sidx[u] = idx;
            if (idx < 2500) {
                const int r = idx / 50, cc = idx % 50;
                const int h = r - 1, w = cc - 1;
                gval[u] = ((unsigned)h < 48u) && ((unsigned)w < 48u);
                goff[u] = h * 48 + w;
            } else { gval[u] = false; goff[u] = 0; }
        }

        float s0[4], c0a[4], s1[4], c1a[4];
#pragma unroll
        for (int k = 0; k < 4; k++) { s0[k] = 0.f; c0a[k] = 0.f; s1[k] = 0.f; c1a[k] = 0.f; }

        float pf[5];
#pragma unroll
        for (int u = 0; u < 5; u++) pf[u] = gval[u] ? x[goff[u]] : 0.0f;

        const int r0 = ty * 2, cc0 = tx * 2;

        for (int ci = 0; ci < CIN; ci++) {
            __syncthreads();
#pragma unroll
            for (int u = 0; u < 5; u++)
                if (sidx[u] < 2500) s_xs[sidx[u]] = pf[u];
            __syncthreads();

            if (ci + 1 < CIN) {
                const float* xn = x + (ci + 1) * HW;
#pragma unroll
                for (int u = 0; u < 5; u++)
                    pf[u] = gval[u] ? xn[goff[u]] : 0.0f;
            }

            float wv0[9], wv1[9];
#pragma unroll
            for (int k = 0; k < 9; k++) wv0[k] = s_wsm[ci * 9 + k];
#pragma unroll
            for (int k = 0; k < 9; k++) wv1[k] = s_wsm[CIN * 9 + ci * 9 + k];

            float p[4][4];
#pragma unroll
            for (int r = 0; r < 4; r++)
#pragma unroll
                for (int cc = 0; cc < 4; cc++)
                    p[r][cc] = s_xs[(r0 + r) * 50 + (cc0 + cc)];

#pragma unroll
            for (int oy = 0; oy < 2; oy++)
#pragma unroll
                for (int ox = 0; ox < 2; ox++) {
                    const int k = oy * 2 + ox;
                    float a = 0.0f;
#pragma unroll
                    for (int kh = 0; kh < 3; kh++)
#pragma unroll
                        for (int kw = 0; kw < 3; kw++)
                            a = fmaf(wv0[kh * 3 + kw], p[oy + kh][ox + kw], a);
                    float y = a - c0a[k];
                    float tt = s0[k] + y;
                    c0a[k] = (tt - s0[k]) - y;
                    s0[k] = tt;

                    float a1 = 0.0f;
#pragma unroll
                    for (int kh = 0; kh < 3; kh++)
#pragma unroll
                        for (int kw = 0; kw < 3; kw++)
                            a1 = fmaf(wv1[kh * 3 + kw], p[oy + kh][ox + kw], a1);
                    y = a1 - c1a[k];
                    tt = s1[k] + y;
                    c1a[k] = (tt - s1[k]) - y;
                    s1[k] = tt;
                }
        }

        const float b0v = bias[co0];
        const float b1v = bias[co1];
#pragma unroll
        for (int oy = 0; oy < 2; oy++)
#pragma unroll
            for (int ox = 0; ox < 2; ox++) {
                const int k = oy * 2 + ox;
                const int pix = (ty * 2 + oy) * 48 + (tx * 2 + ox);
                g_inter[co0 * HW + pix] = (s0[k] + c0a[k]) + b0v;
                g_inter[co1 * HW + pix] = (s1[k] + c1a[k]) + b1v;
            }
    }
    gsync();

    // ================= phase 2: heads (dot + decode), blocks 0-11 ============
    {
        const int m = b * NT + t;
        if (m < M_ANCH) {
            const int a = m / HW;
            const int p = m % HW;
            g_rank[m] = 0;

            const float* dw  = det_w + a * 256;
            const float* r0w = reg_w + (0 * 3 + a) * 256;
            const float* r1w = reg_w + (1 * 3 + a) * 256;
            const float* r2w = reg_w + (2 * 3 + a) * 256;
            const float* r3w = reg_w + (3 * 3 + a) * 256;

            float sa[5], ca[5];
#pragma unroll
            for (int k = 0; k < 5; k++) { sa[k] = 0.0f; ca[k] = 0.0f; }

            for (int cc = 0; cc < 256; cc++) {
                const float v = g_inter[cc * HW + p];
                float pr[5];
                pr[0] = dw[cc]  * v;
                pr[1] = r0w[cc] * v;
                pr[2] = r1w[cc] * v;
                pr[3] = r2w[cc] * v;
                pr[4] = r3w[cc] * v;
#pragma unroll
                for (int k = 0; k < 5; k++) {
                    const float y = pr[k] - ca[k];
                    const float tt = sa[k] + y;
                    ca[k] = (tt - sa[k]) - y;
                    sa[k] = tt;
                }
            }

            const double s  = ((double)sa[0] + (double)ca[0]) + (double)det_b[a];
            const double d0 = ((double)sa[1] + (double)ca[1]) + (double)reg_b[0 * 3 + a];
            const double d1 = ((double)sa[2] + (double)ca[2]) + (double)reg_b[1 * 3 + a];
            const double d2 = ((double)sa[3] + (double)ca[3]) + (double)reg_b[2 * 3 + a];
            const double d3 = ((double)sa[4] + (double)ca[4]) + (double)reg_b[3 * 3 + a];

            const float score = (float)(1.0 / (1.0 + exp(-s)));

            const double x1 = (double)anchors[m * 4 + 0];
            const double y1 = (double)anchors[m * 4 + 1];
            const double x2 = (double)anchors[m * 4 + 2];
            const double y2 = (double)anchors[m * 4 + 3];
            const double aw = x2 - x1;
            const double ah = y2 - y1;
            // replicate reference's swapped center computation exactly
            const double acx = y1 + aw * 0.5;
            const double acy = x1 + ah * 0.5;

            const double px = acx + d0 * aw;
            const double py = acy + d1 * ah;
            const double pw = aw * exp(d2);
            const double ph = ah * exp(d3);

            float b0 = (float)(px - pw * 0.5);
            float b1 = (float)(py - ph * 0.5);
            float b2 = (float)(px + pw * 0.5);
            float b3 = (float)(py + ph * 0.5);
            b0 = fminf(fmaxf(b0, 0.0f), IMGSZ);
            b1 = fminf(fmaxf(b1, 0.0f), IMGSZ);
            b2 = fminf(fmaxf(b2, 0.0f), IMGSZ);
            b3 = fminf(fmaxf(b3, 0.0f), IMGSZ);

            const float hts = b2 - b0;
            const float wds = b3 - b1;
            const bool valid = (hts > 0.0f) && (wds > 0.0f) && (score > OBJ_THR);

            g_skey[m] = valid ? score : NEGV;
            g_boxes[m * 4 + 0] = b0;
            g_boxes[m * 4 + 1] = b1;
            g_boxes[m * 4 + 2] = b2;
            g_boxes[m * 4 + 3] = b3;
        }
    }
    gsync();

    // ============ phase 3a: split rank-count sort, blocks 0-95 ===============
    {
        if (b < 12 * SORT_SPLIT) {
            const int seg  = b / 12;
            const int ablk = b % 12;
            const int i = ablk * NT + t;
            const float si = g_skey[i];
            const int base = seg * SEG;

            for (int idx = t; idx < SEG; idx += NT)
                s_xs[idx] = g_skey[base + idx];
            __syncthreads();

            int cnt = 0;
#pragma unroll 8
            for (int jj = 0; jj < SEG; jj++) {
                const float sj = s_xs[jj];
                const int j = base + jj;
                cnt += (sj > si) || ((sj == si) && (j < i));
            }
            atomicAdd(&g_rank[i], cnt);
        } else if (b == 96) {
            // initialize output: scores=-1, boxes=0
            for (int k = t; k < TOPK; k += NT) {
                out[k] = -1.0f;
                out[TOPK + k * 4 + 0] = 0.0f;
                out[TOPK + k * 4 + 1] = 0.0f;
                out[TOPK + k * 4 + 2] = 0.0f;
                out[TOPK + k * 4 + 3] = 0.0f;
            }
        }
    }
    gsync();

    // ============ phase 3b: scatter order ====================================
    {
        const int g = b * NT + t;
        if (g < M_ANCH) {
            const int r = *((volatile int*)&g_rank[g]);   // L1-bypass (atomics wrote L2)
            g_order[r] = g;
        }
    }
    gsync();

    // ============ phase 4: NMS + compaction, block 0 =========================
    if (b == 0) {
        float* bx  = dyn;                                  // 4*M floats
        float* ssv = dyn + 4 * M_ANCH;                     // M floats
        unsigned char* supp = (unsigned char*)(dyn + 5 * M_ANCH);  // M bytes
        __shared__ float kb[32 * 4];
        __shared__ int   knum;
        __shared__ int   nv_s;
        __shared__ int   soffs[NT];

        for (int i = t; i < M_ANCH; i += NT) {
            const int o = g_order[i];
            ssv[i] = g_skey[o];
            bx[i * 4 + 0] = g_boxes[o * 4 + 0];
            bx[i * 4 + 1] = g_boxes[o * 4 + 1];
            bx[i * 4 + 2] = g_boxes[o * 4 + 2];
            bx[i * 4 + 3] = g_boxes[o * 4 + 3];
            supp[i] = 0;
        }
        if (t == 0) nv_s = 0;
        __syncthreads();

        int cnt = 0;
        for (int i = t; i < M_ANCH; i += NT) cnt += (ssv[i] > -1.0e8f);
        atomicAdd(&nv_s, cnt);
        __syncthreads();
        const int nv = nv_s;

        const unsigned FULL = 0xffffffffu;
        for (int base = 0; base < nv; base += 32) {
            if (t < 32) {
                const int i = base + t;
                const bool inrange = (i < nv);
                bool sup_l = inrange ? (supp[i] != 0) : true;
                float c0 = 0.f, c1 = 0.f, c2 = 0.f, c3 = 0.f;
                if (inrange) {
                    c0 = bx[i * 4 + 0]; c1 = bx[i * 4 + 1];
                    c2 = bx[i * 4 + 2]; c3 = bx[i * 4 + 3];
                }
                unsigned supmask = __ballot_sync(FULL, sup_l);
                const unsigned inmask = __ballot_sync(FULL, inrange);
                for (int k = 0; k < 32; k++) {
                    if (!((inmask >> k) & 1u)) break;
                    if ((supmask >> k) & 1u) continue;
                    const float a0 = __shfl_sync(FULL, c0, k);
                    const float a1 = __shfl_sync(FULL, c1, k);
                    const float a2 = __shfl_sync(FULL, c2, k);
                    const float a3 = __shfl_sync(FULL, c3, k);
                    if (t > k && !sup_l) {
                        const float areai = (a2 - a0) * (a3 - a1);
                        if (iou_f(a0, a1, a2, a3, areai, c0, c1, c2, c3) > IOU_THR)
                            sup_l = true;
                    }
                    supmask = __ballot_sync(FULL, sup_l);
                }
                if (inrange) supp[i] = sup_l ? (unsigned char)1 : (unsigned char)0;
                const unsigned keptmask = (~supmask) & inmask;
                if (inrange && !sup_l) {
                    const int pos = __popc(keptmask & ((1u << t) - 1u));
                    kb[pos * 4 + 0] = c0; kb[pos * 4 + 1] = c1;
                    kb[pos * 4 + 2] = c2; kb[pos * 4 + 3] = c3;
                }
                if (t == 0) knum = __popc(keptmask);
            }
            __syncthreads();
            const int nk = knum;
            if (nk > 0) {
                for (int j = base + 32 + t; j < nv; j += NT) {
                    if (supp[j]) continue;
                    const float d0 = bx[j * 4 + 0], d1 = bx[j * 4 + 1];
                    const float d2 = bx[j * 4 + 2], d3 = bx[j * 4 + 3];
                    bool sflag = false;
                    for (int k = 0; k < nk; k++) {
                        const float a0 = kb[k * 4 + 0], a1 = kb[k * 4 + 1];
                        const float a2 = kb[k * 4 + 2], a3 = kb[k * 4 + 3];
                        const float areai = (a2 - a0) * (a3 - a1);
                        if (iou_f(a0, a1, a2, a3, areai, d0, d1, d2, d3) > IOU_THR) {
                            sflag = true; break;
                        }
                    }
                    if (sflag) supp[j] = 1;
                }
            }
            __syncthreads();
        }

        // stable compaction (out already initialized by block 96)
        const int segsz = (M_ANCH + NT - 1) / NT;   // 12
        const int lo = t * segsz;
        const int hi = min(lo + segsz, nv);
        int c = 0;
        for (int i = lo; i < hi; i++) c += (supp[i] == 0);
        soffs[t] = c;
        __syncthreads();
        if (t == 0) {
            int run = 0;
            for (int k = 0; k < NT; k++) { int tmp = soffs[k]; soffs[k] = run; run += tmp; }
        }
        __syncthreads();
        int r = soffs[t];
        for (int i = lo; i < hi; i++) {
            if (supp[i] == 0) {
                if (r < TOPK) {
                    out[r] = ssv[i];
                    out[TOPK + r * 4 + 0] = bx[i * 4 + 0];
                    out[TOPK + r * 4 + 1] = bx[i * 4 + 1];
                    out[TOPK + r * 4 + 2] = bx[i * 4 + 2];
                    out[TOPK + r * 4 + 3] = bx[i * 4 + 3];
                }
                r++;
            }
        }
    }
}

// ---------------- launch: ONE kernel ----------------
extern "C" void kernel_launch(void* const* d_in, const int* in_sizes, int n_in,
                              void* d_out, int out_size) {
    const float* x       = (const float*)d_in[0];
    const float* conv_w  = (const float*)d_in[1];
    const float* conv_b  = (const float*)d_in[2];
    const float* det_w   = (const float*)d_in[3];
    const float* det_b   = (const float*)d_in[4];
    const float* reg_w   = (const float*)d_in[5];
    const float* reg_b   = (const float*)d_in[6];
    const float* anchors = (const float*)d_in[7];
    float* out = (float*)d_out;

    cudaFuncSetAttribute(fused_kernel, cudaFuncAttributeMaxDynamicSharedMemorySize, NMS_SMEM);
    fused_kernel<<<NB, NT, NMS_SMEM>>>(x, conv_w, conv_b, det_w, det_b,
                                       reg_w, reg_b, anchors, out);
}

// round 7
// speedup vs baseline: 1.1885x; 1.1885x over previous
#include <cuda_runtime.h>
#include <math.h>

#define HH 48
#define WW 48
#define CIN 256
#define COUT 256
#define HW 2304          // 48*48
#define M_ANCH 6912      // 3*48*48
#define TOPK 2000
#define NEGV -1000000000.0f
#define IMGSZ 768.0f
#define OBJ_THR 0.3f
#define IOU_THR 0.7f

// ---------------- scratch (no allocations allowed) ----------------
__device__ float g_inter[COUT * HW];     // conv output, (co, h, w)
__device__ float g_skey[M_ANCH];         // sort key: valid ? score : NEG
__device__ float g_boxes[M_ANCH * 4];    // decoded+clipped boxes
__device__ int   g_order[M_ANCH];        // stable descending argsort
__device__ float g_sbox[M_ANCH * 4];     // boxes gathered in sorted order (nms scratch)

// ---------------- polynomial exp (no libm double exp) ------------------------
// exp(x) for x >= 0 via degree-40 Taylor Horner; negatives via reciprocal.
// rel err <= ~4e-15 for |x| <= 8 (logits here are |x| <~ 2.5).
__device__ __forceinline__ double poly_exp(double x) {
    const double ax = fabs(x);
    double p = 1.0;
#pragma unroll
    for (int k = 40; k >= 1; k--)
        p = fma(p * ax, 1.0 / (double)k, 1.0);   // 1/k folded to constant at compile time
    return (x >= 0.0) ? p : (1.0 / p);
}

// ---------------- 0a/0b) output init (also position heads at launch #4) -----
__global__ void out_init_scores(float* __restrict__ out) {
    const int k = blockIdx.x * 256 + threadIdx.x;
    if (k < TOPK) out[k] = -1.0f;
}
__global__ void out_init_boxes(float* __restrict__ out) {
    const int k = blockIdx.x * 256 + threadIdx.x;
    if (k < TOPK * 4) out[TOPK + k] = 0.0f;
}

// ---------------- 1) 3x3 SAME conv, 256->256, fp32 Kahan, prefetch -----------
// Unchanged from the measured-243us version (bit-identical outputs).
__global__ __launch_bounds__(576, 2)
void conv3_kernel(const float* __restrict__ x,
                  const float* __restrict__ wgt,
                  const float* __restrict__ bias) {
    __shared__ float xs[50 * 50];
    __shared__ float wsm[CIN * 9];
    const int co = blockIdx.x;
    const int t = threadIdx.x;
    const int ty = t / 24, tx = t % 24;

    for (int idx = t; idx < CIN * 9; idx += 576)
        wsm[idx] = wgt[co * CIN * 9 + idx];

    int  goff[5]; bool gval[5]; int sidx[5];
#pragma unroll
    for (int u = 0; u < 5; u++) {
        const int idx = t + u * 576;
        sidx[u] = idx;
        if (idx < 2500) {
            const int r = idx / 50, cc = idx % 50;
            const int h = r - 1, w = cc - 1;
            gval[u] = ((unsigned)h < 48u) && ((unsigned)w < 48u);
            goff[u] = h * 48 + w;
        } else { gval[u] = false; goff[u] = 0; }
    }

    float s[4], c[4];
#pragma unroll
    for (int k = 0; k < 4; k++) { s[k] = 0.0f; c[k] = 0.0f; }

    float pf[5];
#pragma unroll
    for (int u = 0; u < 5; u++) pf[u] = gval[u] ? x[goff[u]] : 0.0f;

    const int r0 = ty * 2, c0 = tx * 2;

    for (int ci = 0; ci < CIN; ci++) {
        __syncthreads();
#pragma unroll
        for (int u = 0; u < 5; u++)
            if (sidx[u] < 2500) xs[sidx[u]] = pf[u];
        __syncthreads();

        if (ci + 1 < CIN) {
            const float* xn = x + (ci + 1) * HW;
#pragma unroll
            for (int u = 0; u < 5; u++)
                pf[u] = gval[u] ? xn[goff[u]] : 0.0f;
        }

        float wv[9];
#pragma unroll
        for (int k = 0; k < 9; k++) wv[k] = wsm[ci * 9 + k];

        float p[4][4];
#pragma unroll
        for (int r = 0; r < 4; r++)
#pragma unroll
            for (int cc = 0; cc < 4; cc++)
                p[r][cc] = xs[(r0 + r) * 50 + (c0 + cc)];

#pragma unroll
        for (int oy = 0; oy < 2; oy++)
#pragma unroll
            for (int ox = 0; ox < 2; ox++) {
                float a = 0.0f;
#pragma unroll
                for (int kh = 0; kh < 3; kh++)
#pragma unroll
                    for (int kw = 0; kw < 3; kw++)
                        a = fmaf(wv[kh * 3 + kw], p[oy + kh][ox + kw], a);
                const int k = oy * 2 + ox;
                const float y = a - c[k];
                const float tt = s[k] + y;
                c[k] = (tt - s[k]) - y;
                s[k] = tt;
            }
    }

    const float b = bias[co];
#pragma unroll
    for (int oy = 0; oy < 2; oy++)
#pragma unroll
        for (int ox = 0; ox < 2; ox++) {
            const int k = oy * 2 + ox;
            const float r = s[k] + c[k];
            g_inter[co * HW + (ty * 2 + oy) * 48 + (tx * 2 + ox)] = r + b;
        }
}

// ---------------- 2) heads: fp32 Kahan dots + poly-exp decode ----------------
__global__ void heads_kernel(const float* __restrict__ det_w,
                             const float* __restrict__ det_b,
                             const float* __restrict__ reg_w,
                             const float* __restrict__ reg_b,
                             const float* __restrict__ anchors) {
    const int m = blockIdx.x * 128 + threadIdx.x;
    if (m >= M_ANCH) return;
    const int a = m / HW;
    const int p = m % HW;

    const float* dw  = det_w + a * 256;
    const float* r0w = reg_w + (0 * 3 + a) * 256;
    const float* r1w = reg_w + (1 * 3 + a) * 256;
    const float* r2w = reg_w + (2 * 3 + a) * 256;
    const float* r3w = reg_w + (3 * 3 + a) * 256;

    float sa[5], ca[5];
#pragma unroll
    for (int k = 0; k < 5; k++) { sa[k] = 0.0f; ca[k] = 0.0f; }

    for (int cc = 0; cc < 256; cc++) {
        const float v = g_inter[cc * HW + p];
        float pr[5];
        pr[0] = dw[cc]  * v;
        pr[1] = r0w[cc] * v;
        pr[2] = r1w[cc] * v;
        pr[3] = r2w[cc] * v;
        pr[4] = r3w[cc] * v;
#pragma unroll
        for (int k = 0; k < 5; k++) {
            const float y = pr[k] - ca[k];
            const float tt = sa[k] + y;
            ca[k] = (tt - sa[k]) - y;
            sa[k] = tt;
        }
    }

    const double s  = ((double)sa[0] + (double)ca[0]) + (double)det_b[a];
    const double d0 = ((double)sa[1] + (double)ca[1]) + (double)reg_b[0 * 3 + a];
    const double d1 = ((double)sa[2] + (double)ca[2]) + (double)reg_b[1 * 3 + a];
    const double d2 = ((double)sa[3] + (double)ca[3]) + (double)reg_b[2 * 3 + a];
    const double d3 = ((double)sa[4] + (double)ca[4]) + (double)reg_b[3 * 3 + a];

    const float score = (float)(1.0 / (1.0 + poly_exp(-s)));

    const double x1 = (double)anchors[m * 4 + 0];
    const double y1 = (double)anchors[m * 4 + 1];
    const double x2 = (double)anchors[m * 4 + 2];
    const double y2 = (double)anchors[m * 4 + 3];
    const double aw = x2 - x1;
    const double ah = y2 - y1;
    // replicate reference's swapped center computation exactly
    const double acx = y1 + aw * 0.5;
    const double acy = x1 + ah * 0.5;

    const double px = acx + d0 * aw;
    const double py = acy + d1 * ah;
    const double pw = aw * poly_exp(d2);
    const double ph = ah * poly_exp(d3);

    float b0 = (float)(px - pw * 0.5);
    float b1 = (float)(py - ph * 0.5);
    float b2 = (float)(px + pw * 0.5);
    float b3 = (float)(py + ph * 0.5);
    b0 = fminf(fmaxf(b0, 0.0f), IMGSZ);
    b1 = fminf(fmaxf(b1, 0.0f), IMGSZ);
    b2 = fminf(fmaxf(b2, 0.0f), IMGSZ);
    b3 = fminf(fmaxf(b3, 0.0f), IMGSZ);

    const float hts = b2 - b0;
    const float wds = b3 - b1;
    const bool valid = (hts > 0.0f) && (wds > 0.0f) && (score > OBJ_THR);

    g_skey[m] = valid ? score : NEGV;
    g_boxes[m * 4 + 0] = b0;
    g_boxes[m * 4 + 1] = b1;
    g_boxes[m * 4 + 2] = b2;
    g_boxes[m * 4 + 3] = b3;
}

// ---------------- 3) stable descending argsort via rank counting -------------
__global__ void sort_kernel() {
    __shared__ float stile[128];
    const int i = blockIdx.x * 128 + threadIdx.x;
    const float si = g_skey[i];
    int rank = 0;
    for (int base = 0; base < M_ANCH; base += 128) {
        stile[threadIdx.x] = g_skey[base + threadIdx.x];
        __syncthreads();
#pragma unroll 8
        for (int k = 0; k < 128; k++) {
            const float sj = stile[k];
            const int j = base + k;
            rank += (sj > si) || ((sj == si) && (j < i));
        }
        __syncthreads();
    }
    g_order[rank] = i;
}

// ---------------- 4) NMS + compaction; static smem only (no attribute) -------
#define NMS_NT 1024

__device__ __forceinline__ float iou_f(float a0, float a1, float a2, float a3,
                                       float areai,
                                       float c0, float c1, float c2, float c3) {
    float iw = fminf(a2, c2) - fmaxf(a0, c0);
    float ih = fminf(a3, c3) - fmaxf(a1, c1);
    iw = fmaxf(iw, 0.0f);
    ih = fmaxf(ih, 0.0f);
    const float inter = iw * ih;
    const float areaj = (c2 - c0) * (c3 - c1);
    return inter / fmaxf(areai + areaj - inter, 1e-9f);
}

__global__ __launch_bounds__(NMS_NT, 1)
void nms_kernel(float* __restrict__ out) {
    __shared__ float ssv[M_ANCH];            // 27.6 KB
    __shared__ unsigned char supp[M_ANCH];   // 6.9 KB
    __shared__ float kb[32 * 4];
    __shared__ int   knum;
    __shared__ int   nv_s;
    __shared__ int   soffs[NMS_NT];          // 4 KB

    const int t = threadIdx.x;
    const int nt = NMS_NT;

    // gather scores + boxes in sorted order (boxes -> global scratch, L1-resident)
    for (int i = t; i < M_ANCH; i += nt) {
        const int o = g_order[i];
        ssv[i] = g_skey[o];
        g_sbox[i * 4 + 0] = g_boxes[o * 4 + 0];
        g_sbox[i * 4 + 1] = g_boxes[o * 4 + 1];
        g_sbox[i * 4 + 2] = g_boxes[o * 4 + 2];
        g_sbox[i * 4 + 3] = g_boxes[o * 4 + 3];
        supp[i] = 0;
    }
    if (t == 0) nv_s = 0;
    __syncthreads();

    // valid entries form a sorted prefix
    int cnt = 0;
    for (int i = t; i < M_ANCH; i += nt) cnt += (ssv[i] > -1.0e8f);
    atomicAdd(&nv_s, cnt);
    __syncthreads();
    const int nv = nv_s;

    const unsigned FULL = 0xffffffffu;
    for (int base = 0; base < nv; base += 32) {
        if (t < 32) {
            const int i = base + t;
            const bool inrange = (i < nv);
            bool sup_l = inrange ? (supp[i] != 0) : true;
            float c0 = 0.f, c1 = 0.f, c2 = 0.f, c3 = 0.f;
            if (inrange) {
                c0 = g_sbox[i * 4 + 0]; c1 = g_sbox[i * 4 + 1];
                c2 = g_sbox[i * 4 + 2]; c3 = g_sbox[i * 4 + 3];
            }
            unsigned supmask = __ballot_sync(FULL, sup_l);
            const unsigned inmask = __ballot_sync(FULL, inrange);
            for (int k = 0; k < 32; k++) {
                if (!((inmask >> k) & 1u)) break;
                if ((supmask >> k) & 1u) continue;
                const float a0 = __shfl_sync(FULL, c0, k);
                const float a1 = __shfl_sync(FULL, c1, k);
                const float a2 = __shfl_sync(FULL, c2, k);
                const float a3 = __shfl_sync(FULL, c3, k);
                if (t > k && !sup_l) {
                    const float areai = (a2 - a0) * (a3 - a1);
                    if (iou_f(a0, a1, a2, a3, areai, c0, c1, c2, c3) > IOU_THR)
                        sup_l = true;
                }
                supmask = __ballot_sync(FULL, sup_l);
            }
            if (inrange) supp[i] = sup_l ? (unsigned char)1 : (unsigned char)0;
            const unsigned keptmask = (~supmask) & inmask;
            if (inrange && !sup_l) {
                const int pos = __popc(keptmask & ((1u << t) - 1u));
                kb[pos * 4 + 0] = c0; kb[pos * 4 + 1] = c1;
                kb[pos * 4 + 2] = c2; kb[pos * 4 + 3] = c3;
            }
            if (t == 0) knum = __popc(keptmask);
        }
        __syncthreads();
        const int nk = knum;
        if (nk > 0) {
            for (int j = base + 32 + t; j < nv; j += nt) {
                if (supp[j]) continue;
                const float d0 = g_sbox[j * 4 + 0], d1 = g_sbox[j * 4 + 1];
                const float d2 = g_sbox[j * 4 + 2], d3 = g_sbox[j * 4 + 3];
                bool sflag = false;
                for (int k = 0; k < nk; k++) {
                    const float a0 = kb[k * 4 + 0], a1 = kb[k * 4 + 1];
                    const float a2 = kb[k * 4 + 2], a3 = kb[k * 4 + 3];
                    const float areai = (a2 - a0) * (a3 - a1);
                    if (iou_f(a0, a1, a2, a3, areai, d0, d1, d2, d3) > IOU_THR) {
                        sflag = true; break;
                    }
                }
                if (sflag) supp[j] = 1;
            }
        }
        __syncthreads();
    }

    // stable compaction (out already initialized by init kernels)
    const int segsz = (M_ANCH + nt - 1) / nt;   // 7
    const int lo = t * segsz;
    const int hi = min(lo + segsz, nv);
    int c = 0;
    for (int i = lo; i < hi; i++) c += (supp[i] == 0);
    soffs[t] = c;
    __syncthreads();
    if (t == 0) {
        int run = 0;
        for (int k = 0; k < NMS_NT; k++) { int tmp = soffs[k]; soffs[k] = run; run += tmp; }
    }
    __syncthreads();
    int r = soffs[t];
    for (int i = lo; i < hi; i++) {
        if (supp[i] == 0) {
            if (r < TOPK) {
                out[r] = ssv[i];
                out[TOPK + r * 4 + 0] = g_sbox[i * 4 + 0];
                out[TOPK + r * 4 + 1] = g_sbox[i * 4 + 1];
                out[TOPK + r * 4 + 2] = g_sbox[i * 4 + 2];
                out[TOPK + r * 4 + 3] = g_sbox[i * 4 + 3];
            }
            r++;
        }
    }
}

// ---------------- launch: 6 kernels, heads at #4, no attribute calls ---------
extern "C" void kernel_launch(void* const* d_in, const int* in_sizes, int n_in,
                              void* d_out, int out_size) {
    const float* x       = (const float*)d_in[0];
    const float* conv_w  = (const float*)d_in[1];
    const float* conv_b  = (const float*)d_in[2];
    const float* det_w   = (const float*)d_in[3];
    const float* det_b   = (const float*)d_in[4];
    const float* reg_w   = (const float*)d_in[5];
    const float* reg_b   = (const float*)d_in[6];
    const float* anchors = (const float*)d_in[7];
    float* out = (float*)d_out;

    out_init_scores<<<8, 256>>>(out);                       // #1
    out_init_boxes<<<32, 256>>>(out);                       // #2
    conv3_kernel<<<COUT, 576>>>(x, conv_w, conv_b);         // #3 (measured 243us)
    heads_kernel<<<M_ANCH / 128, 128>>>(det_w, det_b, reg_w, reg_b, anchors);  // #4 -> profiled
    sort_kernel<<<M_ANCH / 128, 128>>>();                   // #5
    nms_kernel<<<1, NMS_NT>>>(out);                         // #6
}

// round 8
// speedup vs baseline: 1.2667x; 1.0658x over previous
#include <cuda_runtime.h>
#include <math.h>

#define HH 48
#define WW 48
#define CIN 256
#define COUT 256
#define HW 2304          // 48*48
#define M_ANCH 6912      // 3*48*48
#define TOPK 2000
#define NEGV -1000000000.0f
#define IMGSZ 768.0f
#define OBJ_THR 0.3f
#define IOU_THR 0.7f

#define SORT_SPLIT 8
#define SEG (M_ANCH / SORT_SPLIT)   // 864

// ---------------- scratch (no allocations allowed) ----------------
__device__ float g_inter[COUT * HW];     // conv output, (co, h, w)
__device__ float g_skey[M_ANCH];         // sort key: valid ? score : NEG
__device__ float g_boxes[M_ANCH * 4];    // decoded+clipped boxes
__device__ int   g_rank[M_ANCH];         // partial rank accumulators
__device__ int   g_order[M_ANCH];        // stable descending argsort
__device__ float g_sbox[M_ANCH * 4];     // boxes in sorted order (nms scratch)

// ---------------- polynomial exp (no libm double exp) ------------------------
// exp(x) for x >= 0 via degree-40 Taylor Horner; negatives via reciprocal.
// rel err <= ~4e-15 for |x| <= 8 (logits here are |x| <~ 3).
__device__ __forceinline__ double poly_exp(double x) {
    const double ax = fabs(x);
    double p = 1.0;
#pragma unroll
    for (int k = 40; k >= 1; k--)
        p = fma(p * ax, 1.0 / (double)k, 1.0);
    return (x >= 0.0) ? p : (1.0 / p);
}

// ---------------- 0) output init ---------------------------------------------
__global__ void out_init_scores(float* __restrict__ out) {
    const int k = blockIdx.x * 256 + threadIdx.x;
    if (k < TOPK) out[k] = -1.0f;
}
__global__ void out_init_boxes(float* __restrict__ out) {
    const int k = blockIdx.x * 256 + threadIdx.x;
    if (k < TOPK * 4) out[TOPK + k] = 0.0f;
}

// ---------------- 1) 3x3 SAME conv, fp32 Kahan, double-buffered smem ---------
// Bit-identical per-output arithmetic to the measured-243us version; smem
// plane is double-buffered so only ONE __syncthreads per input channel.
__global__ __launch_bounds__(576, 2)
void conv3_kernel(const float* __restrict__ x,
                  const float* __restrict__ wgt,
                  const float* __restrict__ bias) {
    __shared__ float xs[2][50 * 50];
    __shared__ float wsm[CIN * 9];
    const int co = blockIdx.x;
    const int t = threadIdx.x;
    const int ty = t / 24, tx = t % 24;

    for (int idx = t; idx < CIN * 9; idx += 576)
        wsm[idx] = wgt[co * CIN * 9 + idx];

    int  goff[5]; bool gval[5]; int sidx[5];
#pragma unroll
    for (int u = 0; u < 5; u++) {
        const int idx = t + u * 576;
        sidx[u] = idx;
        if (idx < 2500) {
            const int r = idx / 50, cc = idx % 50;
            const int h = r - 1, w = cc - 1;
            gval[u] = ((unsigned)h < 48u) && ((unsigned)w < 48u);
            goff[u] = h * 48 + w;
        } else { gval[u] = false; goff[u] = 0; }
    }

    float s[4], c[4];
#pragma unroll
    for (int k = 0; k < 4; k++) { s[k] = 0.0f; c[k] = 0.0f; }

    // stage ci = 0 into buffer 0
    float pf[5];
#pragma unroll
    for (int u = 0; u < 5; u++) pf[u] = gval[u] ? x[goff[u]] : 0.0f;
#pragma unroll
    for (int u = 0; u < 5; u++)
        if (sidx[u] < 2500) xs[0][sidx[u]] = pf[u];
    __syncthreads();

    const int r0 = ty * 2, c0 = tx * 2;

    for (int ci = 0; ci < CIN; ci++) {
        // prefetch next channel early (overlaps with compute)
        const bool more = (ci + 1 < CIN);
        if (more) {
            const float* xn = x + (ci + 1) * HW;
#pragma unroll
            for (int u = 0; u < 5; u++)
                pf[u] = gval[u] ? xn[goff[u]] : 0.0f;
        }

        float wv[9];
#pragma unroll
        for (int k = 0; k < 9; k++) wv[k] = wsm[ci * 9 + k];

        const float* xcur = xs[ci & 1];
        float p[4][4];
#pragma unroll
        for (int r = 0; r < 4; r++)
#pragma unroll
            for (int cc = 0; cc < 4; cc++)
                p[r][cc] = xcur[(r0 + r) * 50 + (c0 + cc)];

#pragma unroll
        for (int oy = 0; oy < 2; oy++)
#pragma unroll
            for (int ox = 0; ox < 2; ox++) {
                float a = 0.0f;
#pragma unroll
                for (int kh = 0; kh < 3; kh++)
#pragma unroll
                    for (int kw = 0; kw < 3; kw++)
                        a = fmaf(wv[kh * 3 + kw], p[oy + kh][ox + kw], a);
                const int k = oy * 2 + ox;
                const float y = a - c[k];
                const float tt = s[k] + y;
                c[k] = (tt - s[k]) - y;
                s[k] = tt;
            }

        // write next plane into the other buffer; one barrier per iteration
        if (more) {
            float* xnext = xs[(ci + 1) & 1];
#pragma unroll
            for (int u = 0; u < 5; u++)
                if (sidx[u] < 2500) xnext[sidx[u]] = pf[u];
            __syncthreads();
        }
    }

    const float b = bias[co];
#pragma unroll
    for (int oy = 0; oy < 2; oy++)
#pragma unroll
        for (int ox = 0; ox < 2; ox++) {
            const int k = oy * 2 + ox;
            const float r = s[k] + c[k];
            g_inter[co * HW + (ty * 2 + oy) * 48 + (tx * 2 + ox)] = r + b;
        }
}

// ---------------- 2) heads: 8-way channel-split Kahan + fp64 merge/decode ----
// 8 lanes per anchor, each Kahan-sums 32 channels; partials merged exactly
// (to ~1e-15 rel) in double via warp shuffles. Lane 0 decodes.
__global__ void heads_kernel(const float* __restrict__ det_w,
                             const float* __restrict__ det_b,
                             const float* __restrict__ reg_w,
                             const float* __restrict__ reg_b,
                             const float* __restrict__ anchors) {
    const int gid = blockIdx.x * 256 + threadIdx.x;
    const int m = gid >> 3;          // anchor index
    const int lane = gid & 7;        // channel segment
    if (m >= M_ANCH) return;
    const int a = m / HW;
    const int p = m % HW;

    const float* dw  = det_w + a * 256;
    const float* r0w = reg_w + (0 * 3 + a) * 256;
    const float* r1w = reg_w + (1 * 3 + a) * 256;
    const float* r2w = reg_w + (2 * 3 + a) * 256;
    const float* r3w = reg_w + (3 * 3 + a) * 256;

    float sa[5], ca[5];
#pragma unroll
    for (int k = 0; k < 5; k++) { sa[k] = 0.0f; ca[k] = 0.0f; }

    const int cbeg = lane * 32;
#pragma unroll 4
    for (int i = 0; i < 32; i++) {
        const int cc = cbeg + i;
        const float v = g_inter[cc * HW + p];
        float pr[5];
        pr[0] = dw[cc]  * v;
        pr[1] = r0w[cc] * v;
        pr[2] = r1w[cc] * v;
        pr[3] = r2w[cc] * v;
        pr[4] = r3w[cc] * v;
#pragma unroll
        for (int k = 0; k < 5; k++) {
            const float y = pr[k] - ca[k];
            const float tt = sa[k] + y;
            ca[k] = (tt - sa[k]) - y;
            sa[k] = tt;
        }
    }

    // exact-ish merge: per-lane compensated value in double, tree-sum over 8 lanes
    double r[5];
#pragma unroll
    for (int k = 0; k < 5; k++) r[k] = (double)sa[k] + (double)ca[k];
#pragma unroll
    for (int off = 4; off >= 1; off >>= 1) {
#pragma unroll
        for (int k = 0; k < 5; k++)
            r[k] += __shfl_down_sync(0xffffffffu, r[k], off, 8);
    }

    if (lane != 0) return;

    const double s  = r[0] + (double)det_b[a];
    const double d0 = r[1] + (double)reg_b[0 * 3 + a];
    const double d1 = r[2] + (double)reg_b[1 * 3 + a];
    const double d2 = r[3] + (double)reg_b[2 * 3 + a];
    const double d3 = r[4] + (double)reg_b[3 * 3 + a];

    const float score = (float)(1.0 / (1.0 + poly_exp(-s)));

    const double x1 = (double)anchors[m * 4 + 0];
    const double y1 = (double)anchors[m * 4 + 1];
    const double x2 = (double)anchors[m * 4 + 2];
    const double y2 = (double)anchors[m * 4 + 3];
    const double aw = x2 - x1;
    const double ah = y2 - y1;
    // replicate reference's swapped center computation exactly
    const double acx = y1 + aw * 0.5;
    const double acy = x1 + ah * 0.5;

    const double px = acx + d0 * aw;
    const double py = acy + d1 * ah;
    const double pw = aw * poly_exp(d2);
    const double ph = ah * poly_exp(d3);

    float b0 = (float)(px - pw * 0.5);
    float b1 = (float)(py - ph * 0.5);
    float b2 = (float)(px + pw * 0.5);
    float b3 = (float)(py + ph * 0.5);
    b0 = fminf(fmaxf(b0, 0.0f), IMGSZ);
    b1 = fminf(fmaxf(b1, 0.0f), IMGSZ);
    b2 = fminf(fmaxf(b2, 0.0f), IMGSZ);
    b3 = fminf(fmaxf(b3, 0.0f), IMGSZ);

    const float hts = b2 - b0;
    const float wds = b3 - b1;
    const bool valid = (hts > 0.0f) && (wds > 0.0f) && (score > OBJ_THR);

    g_skey[m] = valid ? score : NEGV;
    g_rank[m] = 0;                       // zero rank accumulator for sort
    g_boxes[m * 4 + 0] = b0;
    g_boxes[m * 4 + 1] = b1;
    g_boxes[m * 4 + 2] = b2;
    g_boxes[m * 4 + 3] = b3;
}

// ---------------- 3a) split rank counting (8x parallel over j) ---------------
__global__ void sort_count_kernel() {
    __shared__ float stile[SEG];
    const int ablk = blockIdx.x % 54;
    const int seg  = blockIdx.x / 54;
    const int i = ablk * 128 + threadIdx.x;
    const float si = g_skey[i];
    const int base = seg * SEG;

    for (int idx = threadIdx.x; idx < SEG; idx += 128)
        stile[idx] = g_skey[base + idx];
    __syncthreads();

    int cnt = 0;
#pragma unroll 8
    for (int jj = 0; jj < SEG; jj++) {
        const float sj = stile[jj];
        const int j = base + jj;
        cnt += (sj > si) || ((sj == si) && (j < i));
    }
    atomicAdd(&g_rank[i], cnt);
}

// ---------------- 3b) scatter order ------------------------------------------
__global__ void sort_scatter_kernel() {
    const int g = blockIdx.x * 256 + threadIdx.x;
    if (g < M_ANCH) {
        const int r = *((volatile int*)&g_rank[g]);   // L1-bypass (atomics wrote L2)
        g_order[r] = g;
    }
}

// ---------------- 4) NMS + compaction (static smem) --------------------------
#define NMS_NT 1024

__device__ __forceinline__ float iou_f(float a0, float a1, float a2, float a3,
                                       float areai,
                                       float c0, float c1, float c2, float c3) {
    float iw = fminf(a2, c2) - fmaxf(a0, c0);
    float ih = fminf(a3, c3) - fmaxf(a1, c1);
    iw = fmaxf(iw, 0.0f);
    ih = fmaxf(ih, 0.0f);
    const float inter = iw * ih;
    const float areaj = (c2 - c0) * (c3 - c1);
    return inter / fmaxf(areai + areaj - inter, 1e-9f);
}

__global__ __launch_bounds__(NMS_NT, 1)
void nms_kernel(float* __restrict__ out) {
    __shared__ float ssv[M_ANCH];
    __shared__ unsigned char supp[M_ANCH];
    __shared__ float kb[32 * 4];
    __shared__ int   knum;
    __shared__ int   nv_s;
    __shared__ int   soffs[NMS_NT];

    const int t = threadIdx.x;
    const int nt = NMS_NT;

    for (int i = t; i < M_ANCH; i += nt) {
        const int o = g_order[i];
        ssv[i] = g_skey[o];
        g_sbox[i * 4 + 0] = g_boxes[o * 4 + 0];
        g_sbox[i * 4 + 1] = g_boxes[o * 4 + 1];
        g_sbox[i * 4 + 2] = g_boxes[o * 4 + 2];
        g_sbox[i * 4 + 3] = g_boxes[o * 4 + 3];
        supp[i] = 0;
    }
    if (t == 0) nv_s = 0;
    __syncthreads();

    int cnt = 0;
    for (int i = t; i < M_ANCH; i += nt) cnt += (ssv[i] > -1.0e8f);
    atomicAdd(&nv_s, cnt);
    __syncthreads();
    const int nv = nv_s;

    const unsigned FULL = 0xffffffffu;
    for (int base = 0; base < nv; base += 32) {
        if (t < 32) {
            const int i = base + t;
            const bool inrange = (i < nv);
            bool sup_l = inrange ? (supp[i] != 0) : true;
            float c0 = 0.f, c1 = 0.f, c2 = 0.f, c3 = 0.f;
            if (inrange) {
                c0 = g_sbox[i * 4 + 0]; c1 = g_sbox[i * 4 + 1];
                c2 = g_sbox[i * 4 + 2]; c3 = g_sbox[i * 4 + 3];
            }
            unsigned supmask = __ballot_sync(FULL, sup_l);
            const unsigned inmask = __ballot_sync(FULL, inrange);
            for (int k = 0; k < 32; k++) {
                if (!((inmask >> k) & 1u)) break;
                if ((supmask >> k) & 1u) continue;
                const float a0 = __shfl_sync(FULL, c0, k);
                const float a1 = __shfl_sync(FULL, c1, k);
                const float a2 = __shfl_sync(FULL, c2, k);
                const float a3 = __shfl_sync(FULL, c3, k);
                if (t > k && !sup_l) {
                    const float areai = (a2 - a0) * (a3 - a1);
                    if (iou_f(a0, a1, a2, a3, areai, c0, c1, c2, c3) > IOU_THR)
                        sup_l = true;
                }
                supmask = __ballot_sync(FULL, sup_l);
            }
            if (inrange) supp[i] = sup_l ? (unsigned char)1 : (unsigned char)0;
            const unsigned keptmask = (~supmask) & inmask;
            if (inrange && !sup_l) {
                const int pos = __popc(keptmask & ((1u << t) - 1u));
                kb[pos * 4 + 0] = c0; kb[pos * 4 + 1] = c1;
                kb[pos * 4 + 2] = c2; kb[pos * 4 + 3] = c3;
            }
            if (t == 0) knum = __popc(keptmask);
        }
        __syncthreads();
        const int nk = knum;
        if (nk > 0) {
            for (int j = base + 32 + t; j < nv; j += nt) {
                if (supp[j]) continue;
                const float d0 = g_sbox[j * 4 + 0], d1 = g_sbox[j * 4 + 1];
                const float d2 = g_sbox[j * 4 + 2], d3 = g_sbox[j * 4 + 3];
                bool sflag = false;
                for (int k = 0; k < nk; k++) {
                    const float a0 = kb[k * 4 + 0], a1 = kb[k * 4 + 1];
                    const float a2 = kb[k * 4 + 2], a3 = kb[k * 4 + 3];
                    const float areai = (a2 - a0) * (a3 - a1);
                    if (iou_f(a0, a1, a2, a3, areai, d0, d1, d2, d3) > IOU_THR) {
                        sflag = true; break;
                    }
                }
                if (sflag) supp[j] = 1;
            }
        }
        __syncthreads();
    }

    const int segsz = (M_ANCH + nt - 1) / nt;   // 7
    const int lo = t * segsz;
    const int hi = min(lo + segsz, nv);
    int c = 0;
    for (int i = lo; i < hi; i++) c += (supp[i] == 0);
    soffs[t] = c;
    __syncthreads();
    if (t == 0) {
        int run = 0;
        for (int k = 0; k < NMS_NT; k++) { int tmp = soffs[k]; soffs[k] = run; run += tmp; }
    }
    __syncthreads();
    int r = soffs[t];
    for (int i = lo; i < hi; i++) {
        if (supp[i] == 0) {
            if (r < TOPK) {
                out[r] = ssv[i];
                out[TOPK + r * 4 + 0] = g_sbox[i * 4 + 0];
                out[TOPK + r * 4 + 1] = g_sbox[i * 4 + 1];
                out[TOPK + r * 4 + 2] = g_sbox[i * 4 + 2];
                out[TOPK + r * 4 + 3] = g_sbox[i * 4 + 3];
            }
            r++;
        }
    }
}

// ---------------- launch ----------------
extern "C" void kernel_launch(void* const* d_in, const int* in_sizes, int n_in,
                              void* d_out, int out_size) {
    const float* x       = (const float*)d_in[0];
    const float* conv_w  = (const float*)d_in[1];
    const float* conv_b  = (const float*)d_in[2];
    const float* det_w   = (const float*)d_in[3];
    const float* det_b   = (const float*)d_in[4];
    const float* reg_w   = (const float*)d_in[5];
    const float* reg_b   = (const float*)d_in[6];
    const float* anchors = (const float*)d_in[7];
    float* out = (float*)d_out;

    out_init_scores<<<8, 256>>>(out);                                   // #1
    out_init_boxes<<<32, 256>>>(out);                                   // #2
    conv3_kernel<<<COUT, 576>>>(x, conv_w, conv_b);                     // #3
    heads_kernel<<<M_ANCH * 8 / 256, 256>>>(det_w, det_b, reg_w, reg_b, anchors);  // #4 -> profiled
    sort_count_kernel<<<54 * SORT_SPLIT, 128>>>();                      // #5
    sort_scatter_kernel<<<27, 256>>>();                                 // #6
    nms_kernel<<<1, NMS_NT>>>(out);                                     // #7
}